// round 7
// baseline (speedup 1.0000x reference)
#include <cuda_runtime.h>

// LbpBlock: out = concat([x, pad(x_cat)], ch axis)
//   y[n,o,h,w] = sum_c x[n,c,h,w]*conv_w[o,c]   (c=3, o=64)
//   x_cat interior = sum_l H(y_c - y_shift_l) * exp(w[o,l]), zero border.
// x: (8,3,256,256) f32, conv_w: (64,3), w: (64,8) -> out: (8,67,256,256)
//
// R7: occupancy-first. 256 threads, 16x64 tile, x halo in SMEM (not regs),
// launch_bounds(256,3) -> <=85 regs, smem 58.6KB -> 3 CTAs/SM (24 warps).

#define NN   8
#define CIN  3
#define OCH  64
#define HH   256
#define WW   256
#define TH   16
#define TW   64
#define NCHUNK 16                // 4 channels per chunk (2 f2-pairs)
#define HALO_H (TH + 2)          // 18
#define HALO_W (TW + 2)          // 66
#define HALO_N (HALO_H * HALO_W) // 1188
#define CP   74                  // swizzled float4 row pitch (sw(65)=73)
#define PLANE (HH * WW)

struct SmemLayout {
    float4 sy[2][HALO_H][CP];    // 42624 B  double-buffered y (4ch packed)
    float  sx[3][HALO_N];        // 14256 B  x halo (3 planes)
    float2 sewp[32][8];          // 2048 B   exp(w) channel pairs
    float4 scw4[OCH];            // 1024 B   conv_w rows
};                                // 59952 B

__device__ __forceinline__ int sw(int c) { return c + (c >> 3); }

__global__ __launch_bounds__(256, 3)
void lbp_main(const float* __restrict__ x,
              const float* __restrict__ cw,
              const float* __restrict__ w,
              float* __restrict__ out)
{
    extern __shared__ unsigned char smraw[];
    SmemLayout* sm = (SmemLayout*)smraw;

    const int tid = threadIdx.x;
    const int n   = blockIdx.z;
    const int h0  = blockIdx.y * TH;
    const int w0  = blockIdx.x * TW;

    // ---- weight tables ----
    {
        const int i = tid >> 3, l = tid & 7;      // 256 threads = 32 pairs x 8
        sm->sewp[i][l] = make_float2(__expf(w[(2 * i) * 8 + l]),
                                     __expf(w[(2 * i + 1) * 8 + l]));
    }
    if (tid < OCH)
        sm->scw4[tid] = make_float4(cw[3 * tid], cw[3 * tid + 1],
                                    cw[3 * tid + 2], 0.f);

    // ---- x halo -> smem (5 px / thread), zero-padded at image border ----
    int soff[5];                                  // sy f4 index per owned px
    #pragma unroll
    for (int k = 0; k < 5; k++) {
        const int p = tid + k * 256;
        const int r = p / HALO_W;
        const int c = p - r * HALO_W;
        soff[k] = r * CP + sw(c);
        if (k < 4 || p < HALO_N) {
            const int gh = h0 - 1 + r;
            const int gw = w0 - 1 + c;
            float v0 = 0.f, v1 = 0.f, v2 = 0.f;
            if ((unsigned)gh < HH && (unsigned)gw < WW) {
                const int b = (n * CIN * HH + gh) * WW + gw;
                v0 = x[b];
                v1 = x[b + PLANE];
                v2 = x[b + 2 * PLANE];
            }
            sm->sx[0][p] = v0;
            sm->sx[1][p] = v1;
            sm->sx[2][p] = v2;
        }
    }

    // ---- fused copy: x -> out channels [0,3) for this tile ----
    {
        const float4* x4 = (const float4*)(x + n * CIN * PLANE);
        float4*       o4 = (float4*)(out + n * 67 * PLANE);
        #pragma unroll
        for (int j = 0; j < 3; j++) {             // 768 f4 per tile
            const int f   = tid + j * 256;
            const int c   = f >> 8;               // 256 f4 per channel-tile
            const int rem = f & 255;
            const int rr  = rem >> 4;
            const int cc  = rem & 15;
            const int idx = c * (PLANE / 4) + (h0 + rr) * (WW / 4)
                          + (w0 >> 2) + cc;
            o4[idx] = x4[idx];
        }
    }
    __syncthreads();   // sx / tables visible

    // ---- phase 1: y halo for chunk q from smem-x (FMA + STS) ----
    auto phase1 = [&](int q, float4 (*dst)[CP]) {
        const int o0 = 4 * q;
        const float4 c0 = sm->scw4[o0],     c1 = sm->scw4[o0 + 1];
        const float4 c2 = sm->scw4[o0 + 2], c3 = sm->scw4[o0 + 3];
        #pragma unroll
        for (int k = 0; k < 5; k++) {
            const int p = tid + k * 256;
            if (k < 4 || p < HALO_N) {
                const float a = sm->sx[0][p];
                const float b = sm->sx[1][p];
                const float d = sm->sx[2][p];
                float4 v;
                v.x = fmaf(d, c0.z, fmaf(b, c0.y, a * c0.x));
                v.y = fmaf(d, c1.z, fmaf(b, c1.y, a * c1.x));
                v.z = fmaf(d, c2.z, fmaf(b, c2.y, a * c2.x));
                v.w = fmaf(d, c3.z, fmaf(b, c3.y, a * c3.x));
                ((float4*)dst)[soff[k]] = v;
            }
        }
    };

    phase1(0, sm->sy[0]);
    __syncthreads();

    // thread -> 1 row x 4 cols micro-tile
    const int mc  = tid & 15;                 // col group (4 px)
    const int mr  = tid >> 4;                 // row in tile (0..15)
    const int oh  = h0 + mr;
    const int owb = w0 + 4 * mc;
    const int sc0 = 4 * mc;                   // window halo col base
    const bool hv = ((unsigned)(oh - 1) < (unsigned)(HH - 2));

    for (int ch = 0; ch < NCHUNK; ch++) {
        float4 (*cur)[CP] = sm->sy[ch & 1];
        float4 (*nxt)[CP] = sm->sy[(ch & 1) ^ 1];

        #define LDS2(r, c, p) (((const float2*)&cur[r][sw(c)])[p])

        #pragma unroll
        for (int p = 0; p < 2; p++) {         // channel pair within chunk
            // 3x6 window of float2 (2 channels)
            float2 t0[6], t1[6], t2[6];
            #pragma unroll
            for (int c = 0; c < 6; c++) {
                t0[c] = LDS2(mr,     sc0 + c, p);
                t1[c] = LDS2(mr + 1, sc0 + c, p);
                t2[c] = LDS2(mr + 2, sc0 + c, p);
            }

            // overlap next chunk's conv with the window-load latency
            if (p == 0 && ch + 1 < NCHUNK)
                phase1(ch + 1, nxt);

            // exp(w) for this pair: 8 float2 = 64B contiguous
            const int pairIdx = 2 * ch + p;
            float2 e[8];
            {
                const float4* q4 = (const float4*)&sm->sewp[pairIdx][0];
                #pragma unroll
                for (int qq = 0; qq < 4; qq++) {
                    const float4 u = q4[qq];
                    e[2 * qq]     = make_float2(u.x, u.y);
                    e[2 * qq + 1] = make_float2(u.z, u.w);
                }
            }

            float rA[4], rB[4];
            #pragma unroll
            for (int jj = 0; jj < 4; jj++) {
                const float2 ce = t1[jj + 1];
                float a0 = 0.f, a1 = 0.f;

                #define ACC(S, L) { const float2 s_ = (S);   \
                    if (ce.x > s_.x) a0 += e[L].x;           \
                    if (ce.y > s_.y) a1 += e[L].y; }

                // TL, T, TR, L, BL, B, BR, R (reference shift order)
                ACC(t0[jj    ], 0)
                ACC(t0[jj + 1], 1)
                ACC(t0[jj + 2], 2)
                ACC(t1[jj    ], 3)
                ACC(t2[jj    ], 4)
                ACC(t2[jj + 1], 5)
                ACC(t2[jj + 2], 6)
                ACC(t1[jj + 2], 7)
                #undef ACC

                const int ow = owb + jj;
                const bool v = hv &&
                    ((unsigned)(ow - 1) < (unsigned)(WW - 2));
                rA[jj] = v ? a0 : 0.f;
                rB[jj] = v ? a1 : 0.f;
            }

            // coalesced float4 stores (2 channels x 4 px)
            const int cA = 2 * pairIdx;       // = 4*ch + 2*p
            const int ob = ((n * 67 + 3 + cA) * HH + oh) * WW + owb;
            *(float4*)(out + ob        ) = make_float4(rA[0], rA[1], rA[2], rA[3]);
            *(float4*)(out + ob + PLANE) = make_float4(rB[0], rB[1], rB[2], rB[3]);
        }
        #undef LDS2

        __syncthreads();   // cur reads done; nxt writes visible
    }
}

extern "C" void kernel_launch(void* const* d_in, const int* in_sizes, int n_in,
                              void* d_out, int out_size)
{
    const float* x  = (const float*)d_in[0];
    const float* cw = (const float*)d_in[1];
    const float* w  = (const float*)d_in[2];
    float* out = (float*)d_out;

    const int smbytes = (int)sizeof(SmemLayout);   // 59952
    cudaFuncSetAttribute(lbp_main, cudaFuncAttributeMaxDynamicSharedMemorySize,
                         smbytes);

    dim3 grid(WW / TW, HH / TH, NN);   // (4, 16, 8) = 512 blocks
    lbp_main<<<grid, 256, smbytes>>>(x, cw, w, out);
}

// round 8
// speedup vs baseline: 1.0468x; 1.0468x over previous
#include <cuda_runtime.h>

// LbpBlock: out = concat([x, pad(x_cat)], ch axis)
//   y[n,o,h,w] = sum_c x[n,c,h,w]*conv_w[o,c]   (c=3, o=64)
//   x_cat interior = sum_l H(y_c - y_shift_l) * exp(w[o,l]), zero border.
// x: (8,3,256,256) f32, conv_w: (64,3), w: (64,8) -> out: (8,67,256,256)
//
// R8: occupancy via CTA granularity. 64-thread CTAs (16x32 tile), <=102 regs
// -> 10 CTAs/SM = 20 warps, barrier convoys decorrelated across 10 CTAs.
// Weight tables precomputed once by a pre-kernel (no per-block MUFU storm).

#define NN   8
#define CIN  3
#define OCH  64
#define HH   256
#define WW   256
#define TH   16
#define TW   32
#define NT   64                  // threads per block
#define NCHUNK 16                // 4 channels per chunk (2 f2-pairs)
#define HALO_H (TH + 2)          // 18
#define HALO_W (TW + 2)          // 34
#define HALO_N (HALO_H * HALO_W) // 612
#define XRN  10                  // ceil(612/64)
#define CP   38                  // swizzled f4 row pitch (sw(33)=37)
#define PLANE (HH * WW)

__device__ float2 g_ewp[32][8];  // exp(w) interleaved channel pairs
__device__ float4 g_scw[OCH];    // conv_w rows padded to f4

__device__ __forceinline__ int sw(int c) { return c + (c >> 3); }

__global__ void prep(const float* __restrict__ cw, const float* __restrict__ w)
{
    const int t = threadIdx.x;
    if (t < 256) {
        const int i = t >> 3, l = t & 7;
        g_ewp[i][l] = make_float2(__expf(w[(2 * i) * 8 + l]),
                                  __expf(w[(2 * i + 1) * 8 + l]));
    }
    if (t < OCH)
        g_scw[t] = make_float4(cw[3 * t], cw[3 * t + 1], cw[3 * t + 2], 0.f);
}

__global__ __launch_bounds__(NT, 10)
void lbp_main(const float* __restrict__ x, float* __restrict__ out)
{
    __shared__ float4 sy[HALO_H][CP];    // 10944 B  y (4ch packed)
    __shared__ float  sx[CIN][HALO_N];   //  7344 B  x halo planes
    __shared__ float2 sewp[32][8];       //  2048 B
    __shared__ float4 scw[OCH];          //  1024 B

    const int tid = threadIdx.x;
    const int n   = blockIdx.z;
    const int h0  = blockIdx.y * TH;
    const int w0  = blockIdx.x * TW;

    // ---- tables from precomputed globals (broadcast LDG, L1-resident) ----
    {
        const float4* s4 = (const float4*)g_ewp;          // 128 f4
        float4*       d4 = (float4*)sewp;
        d4[tid]      = s4[tid];
        d4[tid + 64] = s4[tid + 64];
        scw[tid] = g_scw[tid];
    }

    // ---- x halo -> smem (<=10 px / thread), zero-padded at image border ----
    int soff[XRN];                       // sy f4 index per owned halo px
    #pragma unroll
    for (int k = 0; k < XRN; k++) {
        const int p = tid + k * NT;
        const int r = p / HALO_W;
        const int c = p - r * HALO_W;
        soff[k] = r * CP + sw(c);
        if (p < HALO_N) {
            const int gh = h0 - 1 + r;
            const int gw = w0 - 1 + c;
            float v0 = 0.f, v1 = 0.f, v2 = 0.f;
            if ((unsigned)gh < HH && (unsigned)gw < WW) {
                const int b = (n * CIN * HH + gh) * WW + gw;
                v0 = x[b];
                v1 = x[b + PLANE];
                v2 = x[b + 2 * PLANE];
            }
            sx[0][p] = v0;
            sx[1][p] = v1;
            sx[2][p] = v2;
        }
    }

    // ---- fused copy: x -> out channels [0,3) for this 16x32 tile ----
    {
        const float4* x4 = (const float4*)(x + n * CIN * PLANE);
        float4*       o4 = (float4*)(out + n * 67 * PLANE);
        #pragma unroll
        for (int j = 0; j < 6; j++) {            // 384 f4 per tile
            const int f   = tid + j * NT;
            const int c   = f >> 7;              // 128 f4 per channel-tile
            const int rem = f & 127;
            const int rr  = rem >> 3;            // row (16 rows x 8 f4)
            const int cc  = rem & 7;
            const int idx = c * (PLANE / 4) + (h0 + rr) * (WW / 4)
                          + (w0 >> 2) + cc;
            o4[idx] = x4[idx];
        }
    }

    // thread -> 2 rows x 4 cols micro-tile
    const int mc  = tid & 7;                 // col group (4 px)
    const int mrg = tid >> 3;                // row pair (0..7)
    const int hr0 = 2 * mrg;                 // top window halo row
    const int sc0 = 4 * mc;                  // window halo col base
    const int oh0 = h0 + 2 * mrg;
    const int owb = w0 + 4 * mc;

    __syncthreads();   // sx / tables visible

    for (int ch = 0; ch < NCHUNK; ch++) {
        const int o0 = 4 * ch;

        // ---- phase 1: y halo for this chunk (smem-x FMA -> STS f4) ----
        {
            const float4 c0 = scw[o0],     c1 = scw[o0 + 1];
            const float4 c2 = scw[o0 + 2], c3 = scw[o0 + 3];
            #pragma unroll
            for (int k = 0; k < XRN; k++) {
                const int p = tid + k * NT;
                if (p < HALO_N) {
                    const float a = sx[0][p];
                    const float b = sx[1][p];
                    const float d = sx[2][p];
                    float4 v;
                    v.x = fmaf(d, c0.z, fmaf(b, c0.y, a * c0.x));
                    v.y = fmaf(d, c1.z, fmaf(b, c1.y, a * c1.x));
                    v.z = fmaf(d, c2.z, fmaf(b, c2.y, a * c2.x));
                    v.w = fmaf(d, c3.z, fmaf(b, c3.y, a * c3.x));
                    ((float4*)sy)[soff[k]] = v;
                }
            }
        }
        __syncthreads();

        #define LDS2(r, c, p) (((const float2*)&sy[r][sw(c)])[p])

        #pragma unroll
        for (int p = 0; p < 2; p++) {        // channel pair within chunk
            // rolling 3-row window of float2 (2 channels)
            float2 t0[6], t1[6], t2[6];
            #pragma unroll
            for (int c = 0; c < 6; c++) {
                t0[c] = LDS2(hr0,     sc0 + c, p);
                t1[c] = LDS2(hr0 + 1, sc0 + c, p);
                t2[c] = LDS2(hr0 + 2, sc0 + c, p);
            }

            const int pairIdx = 2 * ch + p;
            float2 e[8];
            {
                const float4* q4 = (const float4*)&sewp[pairIdx][0];
                #pragma unroll
                for (int qq = 0; qq < 4; qq++) {
                    const float4 u = q4[qq];
                    e[2 * qq]     = make_float2(u.x, u.y);
                    e[2 * qq + 1] = make_float2(u.z, u.w);
                }
            }

            #pragma unroll
            for (int pr = 0; pr < 2; pr++) { // the 2 pixel rows
                if (pr == 1) {
                    #pragma unroll
                    for (int c = 0; c < 6; c++) {
                        t0[c] = t1[c];
                        t1[c] = t2[c];
                        t2[c] = LDS2(hr0 + 3, sc0 + c, p);
                    }
                }
                const int oh = oh0 + pr;
                const bool hv = ((unsigned)(oh - 1) < (unsigned)(HH - 2));

                float rA[4], rB[4];
                #pragma unroll
                for (int jj = 0; jj < 4; jj++) {
                    const float2 ce = t1[jj + 1];
                    float a0 = 0.f, a1 = 0.f;

                    #define ACC(S, L) { const float2 s_ = (S);   \
                        if (ce.x > s_.x) a0 += e[L].x;           \
                        if (ce.y > s_.y) a1 += e[L].y; }

                    // TL, T, TR, L, BL, B, BR, R (reference shift order)
                    ACC(t0[jj    ], 0)
                    ACC(t0[jj + 1], 1)
                    ACC(t0[jj + 2], 2)
                    ACC(t1[jj    ], 3)
                    ACC(t2[jj    ], 4)
                    ACC(t2[jj + 1], 5)
                    ACC(t2[jj + 2], 6)
                    ACC(t1[jj + 2], 7)
                    #undef ACC

                    const int ow = owb + jj;
                    const bool v = hv &&
                        ((unsigned)(ow - 1) < (unsigned)(WW - 2));
                    rA[jj] = v ? a0 : 0.f;
                    rB[jj] = v ? a1 : 0.f;
                }

                // coalesced float4 stores (2 channels x 4 px)
                const int cA = 4 * ch + 2 * p;
                const int ob = ((n * 67 + 3 + cA) * HH + oh) * WW + owb;
                *(float4*)(out + ob        ) =
                    make_float4(rA[0], rA[1], rA[2], rA[3]);
                *(float4*)(out + ob + PLANE) =
                    make_float4(rB[0], rB[1], rB[2], rB[3]);
            }
        }
        #undef LDS2

        __syncthreads();   // all reads done before next chunk overwrites sy
    }
}

extern "C" void kernel_launch(void* const* d_in, const int* in_sizes, int n_in,
                              void* d_out, int out_size)
{
    const float* x  = (const float*)d_in[0];
    const float* cw = (const float*)d_in[1];
    const float* w  = (const float*)d_in[2];
    float* out = (float*)d_out;

    prep<<<1, 256>>>(cw, w);

    dim3 grid(WW / TW, HH / TH, NN);   // (8, 16, 8) = 1024 blocks
    lbp_main<<<grid, NT>>>(x, out);
}

// round 9
// speedup vs baseline: 1.1793x; 1.1266x over previous
#include <cuda_runtime.h>

// LbpBlock: out = concat([x, pad(x_cat)], ch axis)
//   y[n,o,h,w] = sum_c x[n,c,h,w]*conv_w[o,c]   (c=3, o=64)
//   x_cat interior = sum_l H(y_c - y_shift_l) * exp(w[o,l]), zero border.
// x: (8,3,256,256) f32, conv_w: (64,3), w: (64,8) -> out: (8,67,256,256)
//
// R9: channel-split blocks. Each 128-thread CTA does a 32x32 tile x 8
// channels (2 chunks) -> 4096 CTAs, 16K warps (8x prior parallelism).
// Both chunks' y computed upfront -> ONE barrier per kernel. 5 CTAs/SM.

#define NN   8
#define CIN  3
#define OCH  64
#define HH   256
#define WW   256
#define TH   32
#define TW   32
#define NT   128
#define HALO_H (TH + 2)          // 34
#define HALO_W (TW + 2)          // 34
#define HALO_N (HALO_H * HALO_W) // 1156
#define XRN  10                  // ceil(1156/128)
#define CP   41                  // f4 pitch: 32*41 mod 128 = 32 (4 row-groups
                                 // hit phases 0/32/64/96 -> conflict-free)
#define PLANE (HH * WW)

__device__ float2 g_ewp[32][8];  // exp(w): pair p holds ch 2p,2p+1
__device__ float4 g_scw[OCH];    // conv_w rows padded to f4

__device__ __forceinline__ int sw(int c) { return c + (c >> 3); }

__global__ void prep(const float* __restrict__ cw, const float* __restrict__ w)
{
    const int t = threadIdx.x;
    if (t < 256) {
        const int i = t >> 3, l = t & 7;
        g_ewp[i][l] = make_float2(__expf(w[(2 * i) * 8 + l]),
                                  __expf(w[(2 * i + 1) * 8 + l]));
    }
    if (t < OCH)
        g_scw[t] = make_float4(cw[3 * t], cw[3 * t + 1], cw[3 * t + 2], 0.f);
}

__global__ __launch_bounds__(NT, 5)
void lbp_main(const float* __restrict__ x, float* __restrict__ out)
{
    __shared__ float4 sy[2][HALO_H][CP];   // 44608 B: y for both chunks

    const int tid = threadIdx.x;
    const int n   = blockIdx.z >> 3;       // image
    const int cg  = blockIdx.z & 7;        // channel group (8 ch)
    const int h0  = blockIdx.y * TH;
    const int w0  = blockIdx.x * TW;
    const int o0  = 8 * cg;                // first channel of this block

    // ---- x halo -> registers (<=10 px / thread), zero-padded ----
    float xr[XRN][3];
    int   soff[XRN];
    #pragma unroll
    for (int k = 0; k < XRN; k++) {
        const int p = tid + k * NT;
        const int r = p / HALO_W;
        const int c = p - r * HALO_W;
        soff[k] = r * CP + sw(c);
        float v0 = 0.f, v1 = 0.f, v2 = 0.f;
        if (p < HALO_N) {
            const int gh = h0 - 1 + r;
            const int gw = w0 - 1 + c;
            if ((unsigned)gh < HH && (unsigned)gw < WW) {
                const int b = (n * CIN * HH + gh) * WW + gw;
                v0 = x[b];
                v1 = x[b + PLANE];
                v2 = x[b + 2 * PLANE];
            }
        }
        xr[k][0] = v0; xr[k][1] = v1; xr[k][2] = v2;
    }

    // ---- distributed copy: cg 0..2 each copy one x-plane of this tile ----
    if (cg < 3) {
        const float4* x4 = (const float4*)(x + (n * CIN + cg) * PLANE);
        float4*       o4 = (float4*)(out + (n * 67 + cg) * PLANE);
        #pragma unroll
        for (int j = 0; j < 2; j++) {          // 256 f4 per plane-tile
            const int f  = tid + j * NT;
            const int rr = f >> 3;             // 32 rows x 8 f4
            const int cc = f & 7;
            const int idx = (h0 + rr) * (WW / 4) + (w0 >> 2) + cc;
            o4[idx] = x4[idx];
        }
    }

    // ---- phase 1: y for both chunks (register FMA -> STS f4) ----
    #pragma unroll
    for (int ch = 0; ch < 2; ch++) {
        const int q0 = o0 + 4 * ch;
        const float4 c0 = g_scw[q0],     c1 = g_scw[q0 + 1];
        const float4 c2 = g_scw[q0 + 2], c3 = g_scw[q0 + 3];
        #pragma unroll
        for (int k = 0; k < XRN; k++) {
            if (tid + k * NT < HALO_N) {
                const float a = xr[k][0], b = xr[k][1], d = xr[k][2];
                float4 v;
                v.x = fmaf(d, c0.z, fmaf(b, c0.y, a * c0.x));
                v.y = fmaf(d, c1.z, fmaf(b, c1.y, a * c1.x));
                v.z = fmaf(d, c2.z, fmaf(b, c2.y, a * c2.x));
                v.w = fmaf(d, c3.z, fmaf(b, c3.y, a * c3.x));
                ((float4*)sy[ch])[soff[k]] = v;
            }
        }
    }
    __syncthreads();   // the ONLY block-wide barrier

    // thread -> 2 rows x 4 cols micro-tile
    const int mc  = tid & 7;                 // col group (4 px)
    const int mrg = tid >> 3;                // row pair (0..15)
    const int hr0 = 2 * mrg;                 // top window halo row
    const int sc0 = 4 * mc;                  // window halo col base
    const int oh0 = h0 + 2 * mrg;
    const int owb = w0 + 4 * mc;

    #pragma unroll
    for (int ch = 0; ch < 2; ch++) {
        #define LDS2(r, c, p) (((const float2*)&sy[ch][r][sw(c)])[p])

        #pragma unroll
        for (int p = 0; p < 2; p++) {        // channel pair within chunk
            // rolling 3-row window of float2 (2 channels)
            float2 t0[6], t1[6], t2[6];
            #pragma unroll
            for (int c = 0; c < 6; c++) {
                t0[c] = LDS2(hr0,     sc0 + c, p);
                t1[c] = LDS2(hr0 + 1, sc0 + c, p);
                t2[c] = LDS2(hr0 + 2, sc0 + c, p);
            }

            // exp(w) for this pair: uniform broadcast LDG (L1-hot)
            const int pairIdx = 4 * cg + 2 * ch + p;
            float2 e[8];
            {
                const float4* q4 = (const float4*)&g_ewp[pairIdx][0];
                #pragma unroll
                for (int qq = 0; qq < 4; qq++) {
                    const float4 u = q4[qq];
                    e[2 * qq]     = make_float2(u.x, u.y);
                    e[2 * qq + 1] = make_float2(u.z, u.w);
                }
            }

            #pragma unroll
            for (int pr = 0; pr < 2; pr++) { // the 2 pixel rows
                if (pr == 1) {
                    #pragma unroll
                    for (int c = 0; c < 6; c++) {
                        t0[c] = t1[c];
                        t1[c] = t2[c];
                        t2[c] = LDS2(hr0 + 3, sc0 + c, p);
                    }
                }
                const int oh = oh0 + pr;
                const bool hv = ((unsigned)(oh - 1) < (unsigned)(HH - 2));

                float rA[4], rB[4];
                #pragma unroll
                for (int jj = 0; jj < 4; jj++) {
                    const float2 ce = t1[jj + 1];
                    float a0 = 0.f, a1 = 0.f;

                    #define ACC(S, L) { const float2 s_ = (S);   \
                        if (ce.x > s_.x) a0 += e[L].x;           \
                        if (ce.y > s_.y) a1 += e[L].y; }

                    // TL, T, TR, L, BL, B, BR, R (reference shift order)
                    ACC(t0[jj    ], 0)
                    ACC(t0[jj + 1], 1)
                    ACC(t0[jj + 2], 2)
                    ACC(t1[jj    ], 3)
                    ACC(t2[jj    ], 4)
                    ACC(t2[jj + 1], 5)
                    ACC(t2[jj + 2], 6)
                    ACC(t1[jj + 2], 7)
                    #undef ACC

                    const int ow = owb + jj;
                    const bool v = hv &&
                        ((unsigned)(ow - 1) < (unsigned)(WW - 2));
                    rA[jj] = v ? a0 : 0.f;
                    rB[jj] = v ? a1 : 0.f;
                }

                // coalesced float4 stores (2 channels x 4 px)
                const int cA = o0 + 4 * ch + 2 * p;
                const int ob = ((n * 67 + 3 + cA) * HH + oh) * WW + owb;
                *(float4*)(out + ob        ) =
                    make_float4(rA[0], rA[1], rA[2], rA[3]);
                *(float4*)(out + ob + PLANE) =
                    make_float4(rB[0], rB[1], rB[2], rB[3]);
            }
        }
        #undef LDS2
    }
}

extern "C" void kernel_launch(void* const* d_in, const int* in_sizes, int n_in,
                              void* d_out, int out_size)
{
    const float* x  = (const float*)d_in[0];
    const float* cw = (const float*)d_in[1];
    const float* w  = (const float*)d_in[2];
    float* out = (float*)d_out;

    prep<<<1, 256>>>(cw, w);

    const int smbytes = 0;  // static smem
    (void)smbytes;

    dim3 grid(WW / TW, HH / TH, NN * 8);   // (8, 8, 64) = 4096 blocks
    lbp_main<<<grid, NT>>>(x, out);
}

// round 10
// speedup vs baseline: 1.2004x; 1.0179x over previous
#include <cuda_runtime.h>

// LbpBlock: out = concat([x, pad(x_cat)], ch axis)
//   y[n,o,h,w] = sum_c x[n,c,h,w]*conv_w[o,c]   (c=3, o=64)
//   x_cat interior = sum_l H(y_c - y_shift_l) * exp(w[o,l]), zero border.
// x: (8,3,256,256) f32, conv_w: (64,3), w: (64,8) -> out: (8,67,256,256)
//
// R10: crossbar-minimal. f4 window loads (bank-optimal via sw() at 16B
// granularity), 2x4 micro-tile with row rolling -> 48B/px*4ch window
// traffic (was 96 effective with f2). x halo in smem to fund window regs.

#define NN   8
#define CIN  3
#define OCH  64
#define HH   256
#define WW   256
#define TH   32
#define TW   64
#define NCHUNK 16                // 4 channels per chunk
#define HALO_H (TH + 2)          // 34
#define HALO_W (TW + 2)          // 66
#define HALO_N (HALO_H * HALO_W) // 2244
#define CP   74                  // swizzled f4 row pitch (sw(65)=73)
#define PLANE (HH * WW)

struct SmemLayout {
    float4 sy[2][HALO_H][CP];    // 80512 B  double-buffered y (4ch packed)
    float  sx[CIN][HALO_N];      // 26928 B  x halo planes
    float  sew[OCH][8];          //  2048 B  exp(w)
    float4 scw[OCH];             //  1024 B  conv_w rows
};                                // 110512 B -> 2 CTAs/SM (221KB <= 227KB)

__device__ __forceinline__ int sw(int c) { return c + (c >> 3); }

__global__ __launch_bounds__(256, 2)
void lbp_main(const float* __restrict__ x,
              const float* __restrict__ cw,
              const float* __restrict__ w,
              float* __restrict__ out)
{
    extern __shared__ unsigned char smraw[];
    SmemLayout* sm = (SmemLayout*)smraw;

    const int tid = threadIdx.x;
    const int n   = blockIdx.z;
    const int h0  = blockIdx.y * TH;
    const int w0  = blockIdx.x * TW;

    for (int i = tid; i < OCH * 8; i += 256)
        sm->sew[i >> 3][i & 7] = __expf(w[i]);
    if (tid < OCH)
        sm->scw[tid] = make_float4(cw[3 * tid], cw[3 * tid + 1],
                                   cw[3 * tid + 2], 0.f);

    // ---- x halo -> smem (<=9 px / thread), zero-padded ----
    int soff[9];                          // sy f4 index per owned halo px
    #pragma unroll
    for (int k = 0; k < 9; k++) {
        const int p = tid + k * 256;
        const int r = p / HALO_W;
        const int c = p - r * HALO_W;
        soff[k] = r * CP + sw(c);
        if (k < 8 || p < HALO_N) {
            const int gh = h0 - 1 + r;
            const int gw = w0 - 1 + c;
            float v0 = 0.f, v1 = 0.f, v2 = 0.f;
            if ((unsigned)gh < HH && (unsigned)gw < WW) {
                const int b = (n * CIN * HH + gh) * WW + gw;
                v0 = x[b];
                v1 = x[b + PLANE];
                v2 = x[b + 2 * PLANE];
            }
            sm->sx[0][p] = v0;
            sm->sx[1][p] = v1;
            sm->sx[2][p] = v2;
        }
    }

    // ---- fused copy: x -> out channels [0,3) for this 32x64 tile ----
    {
        const float4* x4 = (const float4*)(x + n * CIN * PLANE);
        float4*       o4 = (float4*)(out + n * 67 * PLANE);
        #pragma unroll
        for (int j = 0; j < 6; j++) {          // 1536 f4 per tile
            const int f   = tid + j * 256;
            const int c   = f >> 9;            // 512 f4 per channel-tile
            const int rem = f & 511;
            const int rr  = rem >> 4;
            const int cc  = rem & 15;
            const int idx = c * (PLANE / 4) + (h0 + rr) * (WW / 4)
                          + (w0 >> 2) + cc;
            o4[idx] = x4[idx];
        }
    }
    __syncthreads();   // sx + tables visible

    // ---- phase 1: y halo for chunk q (smem-x FMA -> STS.128) ----
    auto phase1 = [&](int q, float4 (*dst)[CP]) {
        const int o0 = 4 * q;
        const float4 c0 = sm->scw[o0],     c1 = sm->scw[o0 + 1];
        const float4 c2 = sm->scw[o0 + 2], c3 = sm->scw[o0 + 3];
        #pragma unroll
        for (int k = 0; k < 9; k++) {
            const int p = tid + k * 256;
            if (k < 8 || p < HALO_N) {
                const float a = sm->sx[0][p];
                const float b = sm->sx[1][p];
                const float d = sm->sx[2][p];
                float4 v;
                v.x = fmaf(d, c0.z, fmaf(b, c0.y, a * c0.x));
                v.y = fmaf(d, c1.z, fmaf(b, c1.y, a * c1.x));
                v.z = fmaf(d, c2.z, fmaf(b, c2.y, a * c2.x));
                v.w = fmaf(d, c3.z, fmaf(b, c3.y, a * c3.x));
                ((float4*)dst)[soff[k]] = v;
            }
        }
    };

    phase1(0, sm->sy[0]);

    // thread -> 2 rows x 4 cols micro-tile
    const int mc  = tid & 15;            // col group (4 px)
    const int mrg = tid >> 4;            // row pair (0..15)
    const int hr0 = 2 * mrg;             // top window halo row
    const int sc0 = 4 * mc;              // window halo col base
    const int oh0 = h0 + 2 * mrg;
    const int owb = w0 + 4 * mc;

    // border masks as float multipliers (precomputed once)
    float mk[2][4];
    #pragma unroll
    for (int pr = 0; pr < 2; pr++) {
        const bool hv = ((unsigned)(oh0 + pr - 1) < (unsigned)(HH - 2));
        #pragma unroll
        for (int jj = 0; jj < 4; jj++)
            mk[pr][jj] = (hv && ((unsigned)(owb + jj - 1) < (unsigned)(WW - 2)))
                       ? 1.f : 0.f;
    }
    float* const outB = out + (n * 67 + 3) * PLANE + owb;

    __syncthreads();

    // DOPAIR: one pixel row (pr), one channel pair (fields FX/FY of the f4),
    // rows T (top), M (mid), Bo (bottom) are 6-col f4 arrays.
    #define DOPAIR(T, M, Bo, pr, FX, FY, cA) {                            \
        float e0[8], e1[8];                                               \
        {                                                                 \
            const float4 u0 = *(const float4*)&sm->sew[cA][0];            \
            const float4 u1 = *(const float4*)&sm->sew[cA][4];            \
            e0[0]=u0.x; e0[1]=u0.y; e0[2]=u0.z; e0[3]=u0.w;               \
            e0[4]=u1.x; e0[5]=u1.y; e0[6]=u1.z; e0[7]=u1.w;               \
            const float4 p0 = *(const float4*)&sm->sew[(cA) + 1][0];      \
            const float4 p1 = *(const float4*)&sm->sew[(cA) + 1][4];      \
            e1[0]=p0.x; e1[1]=p0.y; e1[2]=p0.z; e1[3]=p0.w;               \
            e1[4]=p1.x; e1[5]=p1.y; e1[6]=p1.z; e1[7]=p1.w;               \
        }                                                                 \
        float rA[4], rB[4];                                               \
        _Pragma("unroll")                                                 \
        for (int jj = 0; jj < 4; jj++) {                                  \
            const float4 ce = M[jj + 1];                                  \
            float a0 = 0.f, a1 = 0.f;                                     \
            /* TL, T, TR, L, BL, B, BR, R (reference shift order) */      \
            if (ce.FX > T[jj     ].FX) a0 += e0[0];                       \
            if (ce.FY > T[jj     ].FY) a1 += e1[0];                       \
            if (ce.FX > T[jj + 1 ].FX) a0 += e0[1];                       \
            if (ce.FY > T[jj + 1 ].FY) a1 += e1[1];                       \
            if (ce.FX > T[jj + 2 ].FX) a0 += e0[2];                       \
            if (ce.FY > T[jj + 2 ].FY) a1 += e1[2];                       \
            if (ce.FX > M[jj     ].FX) a0 += e0[3];                       \
            if (ce.FY > M[jj     ].FY) a1 += e1[3];                       \
            if (ce.FX > Bo[jj    ].FX) a0 += e0[4];                       \
            if (ce.FY > Bo[jj    ].FY) a1 += e1[4];                       \
            if (ce.FX > Bo[jj + 1].FX) a0 += e0[5];                       \
            if (ce.FY > Bo[jj + 1].FY) a1 += e1[5];                       \
            if (ce.FX > Bo[jj + 2].FX) a0 += e0[6];                       \
            if (ce.FY > Bo[jj + 2].FY) a1 += e1[6];                       \
            if (ce.FX > M[jj + 2 ].FX) a0 += e0[7];                       \
            if (ce.FY > M[jj + 2 ].FY) a1 += e1[7];                       \
            rA[jj] = a0 * mk[pr][jj];                                     \
            rB[jj] = a1 * mk[pr][jj];                                     \
        }                                                                 \
        float* op = outB + (cA) * PLANE + (oh0 + (pr)) * WW;              \
        *(float4*)op           = make_float4(rA[0], rA[1], rA[2], rA[3]); \
        *(float4*)(op + PLANE) = make_float4(rB[0], rB[1], rB[2], rB[3]); \
    }

    for (int ch = 0; ch < NCHUNK; ch++) {
        float4 (*cur)[CP] = sm->sy[ch & 1];
        float4 (*nxt)[CP] = sm->sy[(ch & 1) ^ 1];

        // window rows hr0..hr0+2, all 6 cols (bank-optimal LDS.128)
        float4 Aw[6], Bw[6], Cw[6];
        #pragma unroll
        for (int j = 0; j < 6; j++) {
            Aw[j] = cur[hr0    ][sw(sc0 + j)];
            Bw[j] = cur[hr0 + 1][sw(sc0 + j)];
            Cw[j] = cur[hr0 + 2][sw(sc0 + j)];
        }

        // overlap next chunk's conv with window-load latency
        if (ch + 1 < NCHUNK)
            phase1(ch + 1, nxt);

        // pixel row 0: T=Aw, M=Bw, Bo=Cw
        DOPAIR(Aw, Bw, Cw, 0, x, y, 4 * ch)
        DOPAIR(Aw, Bw, Cw, 0, z, w, 4 * ch + 2)

        // roll: row hr0+3 replaces Aw
        #pragma unroll
        for (int j = 0; j < 6; j++)
            Aw[j] = cur[hr0 + 3][sw(sc0 + j)];

        // pixel row 1: T=Bw, M=Cw, Bo=Aw(new)
        DOPAIR(Bw, Cw, Aw, 1, x, y, 4 * ch)
        DOPAIR(Bw, Cw, Aw, 1, z, w, 4 * ch + 2)

        __syncthreads();   // cur reads done; nxt writes visible
    }
    #undef DOPAIR
}

extern "C" void kernel_launch(void* const* d_in, const int* in_sizes, int n_in,
                              void* d_out, int out_size)
{
    const float* x  = (const float*)d_in[0];
    const float* cw = (const float*)d_in[1];
    const float* w  = (const float*)d_in[2];
    float* out = (float*)d_out;

    const int smbytes = (int)sizeof(SmemLayout);   // 110512
    cudaFuncSetAttribute(lbp_main, cudaFuncAttributeMaxDynamicSharedMemorySize,
                         smbytes);

    dim3 grid(WW / TW, HH / TH, NN);   // (4, 8, 8) = 256 blocks
    lbp_main<<<grid, 256, smbytes>>>(x, cw, w, out);
}

// round 11
// speedup vs baseline: 1.4254x; 1.1874x over previous
#include <cuda_runtime.h>

// LbpBlock: out = concat([x, pad(x_cat)], ch axis)
//   y[n,o,h,w] = sum_c x[n,c,h,w]*conv_w[o,c]   (c=3, o=64)
//   x_cat interior = sum_l H(y_c - y_shift_l) * exp(w[o,l]), zero border.
// x: (8,3,256,256) f32, conv_w: (64,3), w: (64,8) -> out: (8,67,256,256)
//
// R11: cg=8 channel split (8 ch = 2 chunks per block) so the x-halo regs die
// after an upfront fill of BOTH sy buffers -> register budget funds the f4
// shared window (one f4 window load serves both channel pairs). 2 barriers
// per block (was 16). 2048 small CTAs -> work-stealing balance.

#define NN   8
#define CIN  3
#define HH   256
#define WW   256
#define TH   32
#define TW   64
#define NT   256
#define HALO_H 34
#define HALO_W 66
#define HALO_N (HALO_H * HALO_W)   // 2244
#define CP   74                    // swizzled f4 row pitch (sw(65)=73)
#define PLANE (HH * WW)

struct Sm {
    float4 sy[2][HALO_H][CP];      // 80512 B: y for both chunks (8 ch)
    float2 sewp[4][8];             // exp(w) for this block's 4 channel pairs
    float4 scw[8];                 // conv_w rows for this block's 8 channels
};                                  // 80896 B -> 2 CTAs/SM

__device__ __forceinline__ int sw(int c) { return c + (c >> 3); }

__global__ __launch_bounds__(NT, 2)
void lbp_main(const float* __restrict__ x,
              const float* __restrict__ cw,
              const float* __restrict__ w,
              float* __restrict__ out)
{
    extern __shared__ unsigned char raw[];
    Sm* sm = (Sm*)raw;

    const int tid = threadIdx.x;
    const int bz  = blockIdx.z;
    const int n   = bz >> 3;          // image
    const int cg  = bz & 7;           // channel group (8 ch)
    const int o0  = 8 * cg;
    const int h0  = blockIdx.y * TH;
    const int w0  = blockIdx.x * TW;

    // ---- per-block tables (only this block's 8 channels: 32 expf total) ----
    if (tid < 32) {
        const int pi = tid >> 3, l = tid & 7;
        sm->sewp[pi][l] = make_float2(__expf(w[(o0 + 2 * pi) * 8 + l]),
                                      __expf(w[(o0 + 2 * pi + 1) * 8 + l]));
    }
    if (tid < 8)
        sm->scw[tid] = make_float4(cw[3 * (o0 + tid)],
                                   cw[3 * (o0 + tid) + 1],
                                   cw[3 * (o0 + tid) + 2], 0.f);

    // ---- x halo -> registers (<=9 px/thread); DIES after the fills ----
    float xr[9][3];
    int   soff[9];
    #pragma unroll
    for (int k = 0; k < 9; k++) {
        const int p = tid + k * NT;
        const int r = p / HALO_W;
        const int c = p - r * HALO_W;
        soff[k] = r * CP + sw(c);
        float v0 = 0.f, v1 = 0.f, v2 = 0.f;
        if (k < 8 || p < HALO_N) {
            const int gh = h0 - 1 + r;
            const int gw = w0 - 1 + c;
            if ((unsigned)gh < HH && (unsigned)gw < WW) {
                const int b = (n * CIN * HH + gh) * WW + gw;
                v0 = x[b];
                v1 = x[b + PLANE];
                v2 = x[b + 2 * PLANE];
            }
        }
        xr[k][0] = v0; xr[k][1] = v1; xr[k][2] = v2;
    }

    // ---- distributed copy: cg 0..2 copy one x-plane tile each ----
    if (cg < 3) {
        const float4* x4 = (const float4*)(x + (n * CIN + cg) * PLANE);
        float4*       o4 = (float4*)(out + (n * 67 + cg) * PLANE);
        #pragma unroll
        for (int j = 0; j < 2; j++) {          // 512 f4 per 32x64 plane-tile
            const int f  = tid + j * NT;
            const int rr = f >> 4;
            const int cc = f & 15;
            const int idx = (h0 + rr) * (WW / 4) + (w0 >> 2) + cc;
            o4[idx] = x4[idx];
        }
    }
    __syncthreads();   // barrier 1: tables visible

    // ---- fill BOTH chunks' y upfront (register FMA -> STS.128) ----
    #pragma unroll
    for (int ch2 = 0; ch2 < 2; ch2++) {
        const float4 c0 = sm->scw[4 * ch2],     c1 = sm->scw[4 * ch2 + 1];
        const float4 c2 = sm->scw[4 * ch2 + 2], c3 = sm->scw[4 * ch2 + 3];
        #pragma unroll
        for (int k = 0; k < 9; k++) {
            if (k < 8 || tid + k * NT < HALO_N) {
                const float a = xr[k][0], b = xr[k][1], d = xr[k][2];
                float4 v;
                v.x = fmaf(d, c0.z, fmaf(b, c0.y, a * c0.x));
                v.y = fmaf(d, c1.z, fmaf(b, c1.y, a * c1.x));
                v.z = fmaf(d, c2.z, fmaf(b, c2.y, a * c2.x));
                v.w = fmaf(d, c3.z, fmaf(b, c3.y, a * c3.x));
                ((float4*)sm->sy[ch2])[soff[k]] = v;
            }
        }
    }
    __syncthreads();   // barrier 2: the last one

    // ---- phase 2: 2 rows x 4 cols micro-tile, f4 shared window ----
    const int mc  = tid & 15;            // col group (4 px)
    const int mrg = tid >> 4;            // row pair (0..15)
    const int hr0 = 2 * mrg;             // top window halo row
    const int sc0 = 4 * mc;              // window halo col base
    const int oh0 = h0 + 2 * mrg;
    const int owb = w0 + 4 * mc;

    // border masks as float multipliers
    float mk[2][4];
    #pragma unroll
    for (int pr = 0; pr < 2; pr++) {
        const bool hv = ((unsigned)(oh0 + pr - 1) < (unsigned)(HH - 2));
        #pragma unroll
        for (int jj = 0; jj < 4; jj++)
            mk[pr][jj] = (hv && ((unsigned)(owb + jj - 1) < (unsigned)(WW - 2)))
                       ? 1.f : 0.f;
    }
    float* const outB = out + (n * 67 + 3 + o0) * PLANE + owb;

    // DOPAIR: one pixel row (pr), one channel pair (f4 fields FX/FY).
    // T/M/Bo are 6-col f4 row arrays; weights from sewp[pairI].
    #define DOPAIR(T, M, Bo, pr, FX, FY, pairI, cA) {                     \
        float2 e[8];                                                      \
        {                                                                 \
            const float4* q4 = (const float4*)&sm->sewp[pairI][0];        \
            _Pragma("unroll")                                             \
            for (int qq = 0; qq < 4; qq++) {                              \
                const float4 u = q4[qq];                                  \
                e[2 * qq]     = make_float2(u.x, u.y);                    \
                e[2 * qq + 1] = make_float2(u.z, u.w);                    \
            }                                                             \
        }                                                                 \
        float rA[4], rB[4];                                               \
        _Pragma("unroll")                                                 \
        for (int jj = 0; jj < 4; jj++) {                                  \
            const float4 ce = M[jj + 1];                                  \
            float a0 = 0.f, a1 = 0.f;                                     \
            /* TL, T, TR, L, BL, B, BR, R (reference shift order) */      \
            if (ce.FX > T[jj     ].FX) a0 += e[0].x;                      \
            if (ce.FY > T[jj     ].FY) a1 += e[0].y;                      \
            if (ce.FX > T[jj + 1 ].FX) a0 += e[1].x;                      \
            if (ce.FY > T[jj + 1 ].FY) a1 += e[1].y;                      \
            if (ce.FX > T[jj + 2 ].FX) a0 += e[2].x;                      \
            if (ce.FY > T[jj + 2 ].FY) a1 += e[2].y;                      \
            if (ce.FX > M[jj     ].FX) a0 += e[3].x;                      \
            if (ce.FY > M[jj     ].FY) a1 += e[3].y;                      \
            if (ce.FX > Bo[jj    ].FX) a0 += e[4].x;                      \
            if (ce.FY > Bo[jj    ].FY) a1 += e[4].y;                      \
            if (ce.FX > Bo[jj + 1].FX) a0 += e[5].x;                      \
            if (ce.FY > Bo[jj + 1].FY) a1 += e[5].y;                      \
            if (ce.FX > Bo[jj + 2].FX) a0 += e[6].x;                      \
            if (ce.FY > Bo[jj + 2].FY) a1 += e[6].y;                      \
            if (ce.FX > M[jj + 2 ].FX) a0 += e[7].x;                      \
            if (ce.FY > M[jj + 2 ].FY) a1 += e[7].y;                      \
            rA[jj] = a0 * mk[pr][jj];                                     \
            rB[jj] = a1 * mk[pr][jj];                                     \
        }                                                                 \
        float* op = outB + (cA) * PLANE + (oh0 + (pr)) * WW;              \
        *(float4*)op           = make_float4(rA[0], rA[1], rA[2], rA[3]); \
        *(float4*)(op + PLANE) = make_float4(rB[0], rB[1], rB[2], rB[3]); \
    }

    #pragma unroll
    for (int ch2 = 0; ch2 < 2; ch2++) {
        float4 (*cur)[CP] = sm->sy[ch2];

        // window rows hr0..hr0+2 (18 LDS.128, serves BOTH channel pairs)
        float4 A[6], B[6], C[6];
        #pragma unroll
        for (int j = 0; j < 6; j++) {
            A[j] = cur[hr0    ][sw(sc0 + j)];
            B[j] = cur[hr0 + 1][sw(sc0 + j)];
            C[j] = cur[hr0 + 2][sw(sc0 + j)];
        }

        // pixel row 0: T=A, M=B, Bo=C
        DOPAIR(A, B, C, 0, x, y, 2 * ch2,     4 * ch2)
        DOPAIR(A, B, C, 0, z, w, 2 * ch2 + 1, 4 * ch2 + 2)

        // roll: row hr0+3 replaces A
        #pragma unroll
        for (int j = 0; j < 6; j++)
            A[j] = cur[hr0 + 3][sw(sc0 + j)];

        // pixel row 1: T=B, M=C, Bo=A(new)
        DOPAIR(B, C, A, 1, x, y, 2 * ch2,     4 * ch2)
        DOPAIR(B, C, A, 1, z, w, 2 * ch2 + 1, 4 * ch2 + 2)
    }
    #undef DOPAIR
}

extern "C" void kernel_launch(void* const* d_in, const int* in_sizes, int n_in,
                              void* d_out, int out_size)
{
    const float* x  = (const float*)d_in[0];
    const float* cw = (const float*)d_in[1];
    const float* w  = (const float*)d_in[2];
    float* out = (float*)d_out;

    const int smbytes = (int)sizeof(Sm);   // 80896
    cudaFuncSetAttribute(lbp_main, cudaFuncAttributeMaxDynamicSharedMemorySize,
                         smbytes);

    dim3 grid(WW / TW, HH / TH, NN * 8);   // (4, 8, 64) = 2048 blocks
    lbp_main<<<grid, NT, smbytes>>>(x, cw, w, out);
}

// round 12
// speedup vs baseline: 1.6184x; 1.1355x over previous
#include <cuda_runtime.h>

// LbpBlock: out = concat([x, pad(x_cat)], ch axis)
//   y[n,o,h,w] = sum_c x[n,c,h,w]*conv_w[o,c]   (c=3, o=64)
//   x_cat interior = sum_l H(y_c - y_shift_l) * exp(w[o,l]), zero border.
// x: (8,3,256,256) f32, conv_w: (64,3), w: (64,8) -> out: (8,67,256,256)
//
// R12 = R11 engine (cg=8 channel split, upfront dual-buffer y fill, f4
// shared window, 2x4 micro-tile) with replicated setup stripped:
// shift-only halo indexing (f4 interior + scalar edges, no divisions),
// conv weights via broadcast LDG (no table barrier -> ONE barrier/block),
// copy work spread over all 8 channel groups.

#define NN   8
#define CIN  3
#define HH   256
#define WW   256
#define TH   32
#define TW   64
#define NT   256
#define HALO_H 34
#define HALO_W 66
#define CP   74                    // swizzled f4 row pitch (sw(65)=73)
#define PLANE (HH * WW)
#define NF4  544                   // interior f4 slots: 34 rows x 16
#define NSLOT (NF4 + 68)           // + scalar edge slots (34 rows x 2)

struct Sm {
    float4 sy[2][HALO_H][CP];      // 80512 B: y for both chunks (8 ch)
    float2 sewp[4][8];             // exp(w) for this block's 4 channel pairs
};                                  // 80768 B -> 2 CTAs/SM

__device__ __forceinline__ int sw(int c) { return c + (c >> 3); }

__global__ __launch_bounds__(NT, 2)
void lbp_main(const float* __restrict__ x,
              const float* __restrict__ cw,
              const float* __restrict__ w,
              float* __restrict__ out)
{
    extern __shared__ unsigned char raw[];
    Sm* sm = (Sm*)raw;

    const int tid = threadIdx.x;
    const int bz  = blockIdx.z;
    const int n   = bz >> 3;          // image
    const int cg  = bz & 7;           // channel group (8 ch)
    const int o0  = 8 * cg;
    const int h0  = blockIdx.y * TH;
    const int w0  = blockIdx.x * TW;

    // ---- exp(w) for this block's 4 channel pairs (32 expf total) ----
    if (tid < 32) {
        const int pi = tid >> 3, l = tid & 7;
        sm->sewp[pi][l] = make_float2(__expf(w[(o0 + 2 * pi) * 8 + l]),
                                      __expf(w[(o0 + 2 * pi + 1) * 8 + l]));
    }

    // ---- conv weights: 6 broadcast LDG.128 (24*cg % 4 == 0 -> aligned) ----
    const float4* cw4 = (const float4*)(cw + 3 * o0);
    const float4 A0 = cw4[0], A1 = cw4[1], A2 = cw4[2];   // chunk 0 (4 ch)
    const float4 B0 = cw4[3], B1 = cw4[4], B2 = cw4[5];   // chunk 1 (4 ch)

    // ---- x halo -> registers, shift-only indexing ----
    // slot s < NF4: interior f4 (row r = s>>4, 4 px at halo col 1+4q)
    // slot s >= NF4: scalar edge (row (s-NF4)>>1, col 0 or 65)
    float xs[3][3][4];                // [k][plane][px]
    int   rk[3], ck[3], tk[3];        // row, first halo col, type(0=f4,1=sc,2=none)
    #pragma unroll
    for (int k = 0; k < 3; k++) {
        const int s = tid + k * NT;
        #pragma unroll
        for (int p = 0; p < 3; p++)
            #pragma unroll
            for (int i = 0; i < 4; i++)
                xs[k][p][i] = 0.f;
        if (s < NF4) {
            const int r = s >> 4, q = s & 15;
            rk[k] = r; ck[k] = 1 + 4 * q; tk[k] = 0;
            const int gh = h0 - 1 + r;
            if ((unsigned)gh < HH) {
                const int base = (n * CIN * HH + gh) * WW + (w0 + 4 * q);
                #pragma unroll
                for (int p = 0; p < 3; p++) {
                    const float4 t = *(const float4*)(x + base + p * PLANE);
                    xs[k][p][0] = t.x; xs[k][p][1] = t.y;
                    xs[k][p][2] = t.z; xs[k][p][3] = t.w;
                }
            }
        } else if (s < NSLOT) {
            const int e2 = s - NF4;
            const int r = e2 >> 1, side = e2 & 1;
            rk[k] = r; ck[k] = side ? 65 : 0; tk[k] = 1;
            const int gh = h0 - 1 + r;
            const int gw = w0 - 1 + ck[k];
            if ((unsigned)gh < HH && (unsigned)gw < WW) {
                const int base = (n * CIN * HH + gh) * WW + gw;
                #pragma unroll
                for (int p = 0; p < 3; p++)
                    xs[k][p][0] = x[base + p * PLANE];
            }
        } else {
            rk[k] = 0; ck[k] = 0; tk[k] = 2;
        }
    }

    // ---- distributed copy: every block copies 192 f4 of its tile ----
    if (tid < 192) {
        const float4* x4 = (const float4*)(x + n * CIN * PLANE);
        float4*       o4 = (float4*)(out + n * 67 * PLANE);
        const int f   = cg * 192 + tid;      // 1536 f4 per tile / 8 groups
        const int c   = f >> 9;
        const int rem = f & 511;
        const int rr  = rem >> 4;
        const int cc  = rem & 15;
        const int idx = c * (PLANE / 4) + (h0 + rr) * (WW / 4) + (w0 >> 2) + cc;
        o4[idx] = x4[idx];
    }

    // ---- fill BOTH chunks' y (register FMA -> STS.128), no barrier needed ----
    #pragma unroll
    for (int ch2 = 0; ch2 < 2; ch2++) {
        const float4 W0 = ch2 ? B0 : A0;
        const float4 W1 = ch2 ? B1 : A1;
        const float4 W2 = ch2 ? B2 : A2;
        // per-channel weights: ch0=(W0.x,W0.y,W0.z) ch1=(W0.w,W1.x,W1.y)
        //                      ch2=(W1.z,W1.w,W2.x) ch3=(W2.y,W2.z,W2.w)
        #pragma unroll
        for (int k = 0; k < 3; k++) {
            if (tk[k] == 0) {
                #pragma unroll
                for (int i = 0; i < 4; i++) {
                    const float a = xs[k][0][i], b = xs[k][1][i], d = xs[k][2][i];
                    float4 v;
                    v.x = fmaf(d, W0.z, fmaf(b, W0.y, a * W0.x));
                    v.y = fmaf(d, W1.y, fmaf(b, W1.x, a * W0.w));
                    v.z = fmaf(d, W2.x, fmaf(b, W1.w, a * W1.z));
                    v.w = fmaf(d, W2.w, fmaf(b, W2.z, a * W2.y));
                    sm->sy[ch2][rk[k]][sw(ck[k] + i)] = v;
                }
            } else if (tk[k] == 1) {
                const float a = xs[k][0][0], b = xs[k][1][0], d = xs[k][2][0];
                float4 v;
                v.x = fmaf(d, W0.z, fmaf(b, W0.y, a * W0.x));
                v.y = fmaf(d, W1.y, fmaf(b, W1.x, a * W0.w));
                v.z = fmaf(d, W2.x, fmaf(b, W1.w, a * W1.z));
                v.w = fmaf(d, W2.w, fmaf(b, W2.z, a * W2.y));
                sm->sy[ch2][rk[k]][sw(ck[k])] = v;
            }
        }
    }
    __syncthreads();   // the ONLY barrier

    // ---- phase 2: 2 rows x 4 cols micro-tile, f4 shared window ----
    const int mc  = tid & 15;            // col group (4 px)
    const int mrg = tid >> 4;            // row pair (0..15)
    const int hr0 = 2 * mrg;             // top window halo row
    const int sc0 = 4 * mc;              // window halo col base
    const int oh0 = h0 + 2 * mrg;
    const int owb = w0 + 4 * mc;

    float mk[2][4];
    #pragma unroll
    for (int pr = 0; pr < 2; pr++) {
        const bool hv = ((unsigned)(oh0 + pr - 1) < (unsigned)(HH - 2));
        #pragma unroll
        for (int jj = 0; jj < 4; jj++)
            mk[pr][jj] = (hv && ((unsigned)(owb + jj - 1) < (unsigned)(WW - 2)))
                       ? 1.f : 0.f;
    }
    float* const outB = out + (n * 67 + 3 + o0) * PLANE + owb;

    #define DOPAIR(T, M, Bo, pr, FX, FY, pairI, cA) {                     \
        float2 e[8];                                                      \
        {                                                                 \
            const float4* q4 = (const float4*)&sm->sewp[pairI][0];        \
            _Pragma("unroll")                                             \
            for (int qq = 0; qq < 4; qq++) {                              \
                const float4 u = q4[qq];                                  \
                e[2 * qq]     = make_float2(u.x, u.y);                    \
                e[2 * qq + 1] = make_float2(u.z, u.w);                    \
            }                                                             \
        }                                                                 \
        float rA[4], rB[4];                                               \
        _Pragma("unroll")                                                 \
        for (int jj = 0; jj < 4; jj++) {                                  \
            const float4 ce = M[jj + 1];                                  \
            float a0 = 0.f, a1 = 0.f;                                     \
            /* TL, T, TR, L, BL, B, BR, R (reference shift order) */      \
            if (ce.FX > T[jj     ].FX) a0 += e[0].x;                      \
            if (ce.FY > T[jj     ].FY) a1 += e[0].y;                      \
            if (ce.FX > T[jj + 1 ].FX) a0 += e[1].x;                      \
            if (ce.FY > T[jj + 1 ].FY) a1 += e[1].y;                      \
            if (ce.FX > T[jj + 2 ].FX) a0 += e[2].x;                      \
            if (ce.FY > T[jj + 2 ].FY) a1 += e[2].y;                      \
            if (ce.FX > M[jj     ].FX) a0 += e[3].x;                      \
            if (ce.FY > M[jj     ].FY) a1 += e[3].y;                      \
            if (ce.FX > Bo[jj    ].FX) a0 += e[4].x;                      \
            if (ce.FY > Bo[jj    ].FY) a1 += e[4].y;                      \
            if (ce.FX > Bo[jj + 1].FX) a0 += e[5].x;                      \
            if (ce.FY > Bo[jj + 1].FY) a1 += e[5].y;                      \
            if (ce.FX > Bo[jj + 2].FX) a0 += e[6].x;                      \
            if (ce.FY > Bo[jj + 2].FY) a1 += e[6].y;                      \
            if (ce.FX > M[jj + 2 ].FX) a0 += e[7].x;                      \
            if (ce.FY > M[jj + 2 ].FY) a1 += e[7].y;                      \
            rA[jj] = a0 * mk[pr][jj];                                     \
            rB[jj] = a1 * mk[pr][jj];                                     \
        }                                                                 \
        float* op = outB + (cA) * PLANE + (oh0 + (pr)) * WW;              \
        *(float4*)op           = make_float4(rA[0], rA[1], rA[2], rA[3]); \
        *(float4*)(op + PLANE) = make_float4(rB[0], rB[1], rB[2], rB[3]); \
    }

    #pragma unroll
    for (int ch2 = 0; ch2 < 2; ch2++) {
        float4 (*cur)[CP] = sm->sy[ch2];

        // window rows hr0..hr0+2 (18 LDS.128, serves BOTH channel pairs)
        float4 A[6], B[6], C[6];
        #pragma unroll
        for (int j = 0; j < 6; j++) {
            A[j] = cur[hr0    ][sw(sc0 + j)];
            B[j] = cur[hr0 + 1][sw(sc0 + j)];
            C[j] = cur[hr0 + 2][sw(sc0 + j)];
        }

        // pixel row 0: T=A, M=B, Bo=C
        DOPAIR(A, B, C, 0, x, y, 2 * ch2,     4 * ch2)
        DOPAIR(A, B, C, 0, z, w, 2 * ch2 + 1, 4 * ch2 + 2)

        // roll: row hr0+3 replaces A
        #pragma unroll
        for (int j = 0; j < 6; j++)
            A[j] = cur[hr0 + 3][sw(sc0 + j)];

        // pixel row 1: T=B, M=C, Bo=A(new)
        DOPAIR(B, C, A, 1, x, y, 2 * ch2,     4 * ch2)
        DOPAIR(B, C, A, 1, z, w, 2 * ch2 + 1, 4 * ch2 + 2)
    }
    #undef DOPAIR
}

extern "C" void kernel_launch(void* const* d_in, const int* in_sizes, int n_in,
                              void* d_out, int out_size)
{
    const float* x  = (const float*)d_in[0];
    const float* cw = (const float*)d_in[1];
    const float* w  = (const float*)d_in[2];
    float* out = (float*)d_out;

    const int smbytes = (int)sizeof(Sm);   // 80768
    cudaFuncSetAttribute(lbp_main, cudaFuncAttributeMaxDynamicSharedMemorySize,
                         smbytes);

    dim3 grid(WW / TW, HH / TH, NN * 8);   // (4, 8, 64) = 2048 blocks
    lbp_main<<<grid, NT, smbytes>>>(x, cw, w, out);
}